// round 1
// baseline (speedup 1.0000x reference)
#include <cuda_runtime.h>
#include <math.h>

// ---------------- problem constants ----------------
#define BQ 32          // batch
#define H 2048         // hidden
#define NH 32          // query heads
#define NKV 8          // kv heads
#define HD 64          // head dim
#define GQ 4           // NH / NKV
#define INTER 8192     // mlp intermediate
#define NBLK 256       // blocks per seq
#define BSZ 16         // block size
#define NSPLIT 8
#define SPLIT_LEN 512  // 4096 / NSPLIT

// ---------------- scratch (device globals; no allocs allowed) ----------------
__device__ float g_normed[BQ * H];
__device__ float g_qkv[BQ * 3072];       // q[2048] | k[512] | v[512] per batch
__device__ float g_attn[BQ * H];
__device__ float g_x1[BQ * H];
__device__ float g_n2[BQ * H];
__device__ float g_act[BQ * INTER];
__device__ float g_pacc[BQ * NKV * NSPLIT * GQ * HD];
__device__ float g_pm[BQ * NKV * NSPLIT * GQ];
__device__ float g_pl[BQ * NKV * NSPLIT * GQ];
// gemm partials (K-split)
__device__ float p_qkv[16 * BQ * 3072];
__device__ float p_o[16 * BQ * 2048];
__device__ float p_g[8 * BQ * INTER];
__device__ float p_u[8 * BQ * INTER];
__device__ float p_d[32 * BQ * 2048];

// ---------------- RMSNorm ----------------
__global__ __launch_bounds__(256) void rmsnorm_kernel(
    const float* __restrict__ x, const float* __restrict__ w, float* __restrict__ o)
{
    int b = blockIdx.x, t = threadIdx.x;
    const float* xr = x + b * H;
    float ss = 0.f;
    for (int i = t; i < H; i += 256) { float v = xr[i]; ss += v * v; }
    __shared__ float red[256];
    red[t] = ss; __syncthreads();
    for (int s = 128; s > 0; s >>= 1) {
        if (t < s) red[t] += red[t + s];
        __syncthreads();
    }
    float inv = rsqrtf(red[0] / (float)H + 1e-5f);
    for (int i = t; i < H; i += 256) o[b * H + i] = xr[i] * inv * w[i];
}

// ---------------- QKV projection (partial over K) ----------------
// grid (12, 16), block 128. 256 output cols per block (segments q/k/v aligned to 256).
__global__ __launch_bounds__(128) void qkv_part_kernel(
    const float* __restrict__ qw, const float* __restrict__ kw, const float* __restrict__ vw)
{
    __shared__ float sm[32][32];
    int t = threadIdx.x;
    int j0 = blockIdx.x * 256;
    int kbase = blockIdx.y * 128;
    const float* W; int n; int jl;
    if (j0 < 2048)      { W = qw; n = 2048; jl = j0; }
    else if (j0 < 2560) { W = kw; n = 512;  jl = j0 - 2048; }
    else                { W = vw; n = 512;  jl = j0 - 2560; }
    jl += t;
    float acc0[32], acc1[32];
#pragma unroll
    for (int b = 0; b < 32; b++) { acc0[b] = 0.f; acc1[b] = 0.f; }
    for (int k0 = 0; k0 < 128; k0 += 32) {
        __syncthreads();
#pragma unroll
        for (int i = t; i < 1024; i += 128) {
            int b = i >> 5, kk = i & 31;
            sm[b][kk] = g_normed[b * H + kbase + k0 + kk];
        }
        __syncthreads();
#pragma unroll 4
        for (int kk = 0; kk < 32; kk++) {
            const float* Wr = W + (kbase + k0 + kk) * n;
            float w0 = Wr[jl], w1 = Wr[jl + 128];
#pragma unroll
            for (int b = 0; b < 32; b++) {
                float a = sm[b][kk];
                acc0[b] = fmaf(a, w0, acc0[b]);
                acc1[b] = fmaf(a, w1, acc1[b]);
            }
        }
    }
    float* P = p_qkv + blockIdx.y * (32 * 3072);
#pragma unroll
    for (int b = 0; b < 32; b++) {
        P[b * 3072 + j0 + t]       = acc0[b];
        P[b * 3072 + j0 + 128 + t] = acc1[b];
    }
}

// ---------------- generic single-matrix GEMM partial ----------------
// C_part[ks][b][n], grid (n/256, K/KC), block 128, 2 cols/thread.
__global__ __launch_bounds__(128) void gemm_part_kernel(
    const float* __restrict__ A, int lda,
    const float* __restrict__ W, int n,
    float* __restrict__ P, int KC)
{
    __shared__ float sm[32][32];
    int t = threadIdx.x;
    int j = blockIdx.x * 256 + t;
    int kbase = blockIdx.y * KC;
    float acc0[32], acc1[32];
#pragma unroll
    for (int b = 0; b < 32; b++) { acc0[b] = 0.f; acc1[b] = 0.f; }
    for (int k0 = 0; k0 < KC; k0 += 32) {
        __syncthreads();
#pragma unroll
        for (int i = t; i < 1024; i += 128) {
            int b = i >> 5, kk = i & 31;
            sm[b][kk] = A[b * lda + kbase + k0 + kk];
        }
        __syncthreads();
#pragma unroll 4
        for (int kk = 0; kk < 32; kk++) {
            const float* Wr = W + (kbase + k0 + kk) * n;
            float w0 = Wr[j], w1 = Wr[j + 128];
#pragma unroll
            for (int b = 0; b < 32; b++) {
                float a = sm[b][kk];
                acc0[b] = fmaf(a, w0, acc0[b]);
                acc1[b] = fmaf(a, w1, acc1[b]);
            }
        }
    }
    float* Pp = P + blockIdx.y * (32 * n);
#pragma unroll
    for (int b = 0; b < 32; b++) {
        Pp[b * n + j]       = acc0[b];
        Pp[b * n + j + 128] = acc1[b];
    }
}

// ---------------- gate+up fused partial ----------------
// grid (64, 8), block 128, 1 col/thread, two weight matrices.
__global__ __launch_bounds__(128) void gu_part_kernel(
    const float* __restrict__ gw, const float* __restrict__ uw)
{
    __shared__ float sm[32][32];
    int t = threadIdx.x;
    int j = blockIdx.x * 128 + t;
    int kbase = blockIdx.y * 256;
    float accg[32], accu[32];
#pragma unroll
    for (int b = 0; b < 32; b++) { accg[b] = 0.f; accu[b] = 0.f; }
    for (int k0 = 0; k0 < 256; k0 += 32) {
        __syncthreads();
#pragma unroll
        for (int i = t; i < 1024; i += 128) {
            int b = i >> 5, kk = i & 31;
            sm[b][kk] = g_n2[b * H + kbase + k0 + kk];
        }
        __syncthreads();
#pragma unroll 4
        for (int kk = 0; kk < 32; kk++) {
            int krow = kbase + k0 + kk;
            float wg = gw[krow * INTER + j];
            float wu = uw[krow * INTER + j];
#pragma unroll
            for (int b = 0; b < 32; b++) {
                float a = sm[b][kk];
                accg[b] = fmaf(a, wg, accg[b]);
                accu[b] = fmaf(a, wu, accu[b]);
            }
        }
    }
    float* Pg = p_g + blockIdx.y * (32 * INTER);
    float* Pu = p_u + blockIdx.y * (32 * INTER);
#pragma unroll
    for (int b = 0; b < 32; b++) {
        Pg[b * INTER + j] = accg[b];
        Pu[b * INTER + j] = accu[b];
    }
}

// ---------------- reduces ----------------
__global__ void reduce_kernel(const float* __restrict__ P, int total, int KS,
                              const float* __restrict__ res, float* __restrict__ out)
{
    int i = blockIdx.x * 256 + threadIdx.x;
    if (i >= total) return;
    float v = res ? res[i] : 0.f;
    for (int s = 0; s < KS; s++) v += P[s * total + i];
    out[i] = v;
}

__global__ void gu_reduce_kernel()
{
    int i = blockIdx.x * 256 + threadIdx.x;   // 32*8192
    const int total = BQ * INTER;
    float gv = 0.f, uv = 0.f;
    for (int s = 0; s < 8; s++) {
        gv += p_g[s * total + i];
        uv += p_u[s * total + i];
    }
    float act = gv * (1.f / (1.f + __expf(-gv))) * uv;
    g_act[i] = act;
}

// ---------------- RoPE (in-place on g_qkv: q heads + k heads) ----------------
__global__ __launch_bounds__(256) void rope_kernel(const int* __restrict__ seqlens)
{
    int b = blockIdx.x;
    float fp = (float)seqlens[b];
    for (int slot = threadIdx.x; slot < 40 * 32; slot += 256) {
        int head = slot >> 5, i = slot & 31;
        float inv = expf(-(float)i * (9.210340371976184f / 32.f)); // 10000^{-i/32}
        float ang = fp * inv;
        float s, c;
        sincosf(ang, &s, &c);
        float* p;
        if (head < 32) p = g_qkv + b * 3072 + head * 64 + i;
        else           p = g_qkv + b * 3072 + 2048 + (head - 32) * 64 + i;
        float x1 = p[0], x2 = p[32];
        p[0]  = x1 * c - x2 * s;
        p[32] = x2 * c + x1 * s;
    }
}

// ---------------- split-KV decode attention ----------------
__global__ __launch_bounds__(128) void attn_kernel(
    const float* __restrict__ kc, const float* __restrict__ vc,
    const int* __restrict__ bt, const int* __restrict__ seqlens)
{
    int sp = blockIdx.x, kvh = blockIdx.y, b = blockIdx.z;
    int tid = threadIdx.x, wid = tid >> 5, lane = tid & 31;
    int seqlen = seqlens[b];
    int total = seqlen + 1;
    int start = sp * SPLIT_LEN;
    int end = min(start + SPLIT_LEN, total);

    float2 q[GQ];
#pragma unroll
    for (int g = 0; g < GQ; g++) {
        const float* qp = g_qkv + b * 3072 + (kvh * GQ + g) * HD + 2 * lane;
        q[g].x = qp[0] * 0.125f;   // 1/sqrt(64)
        q[g].y = qp[1] * 0.125f;
    }
    float m[GQ], l[GQ];
    float2 acc[GQ];
#pragma unroll
    for (int g = 0; g < GQ; g++) { m[g] = -1e30f; l[g] = 0.f; acc[g].x = 0.f; acc[g].y = 0.f; }

    for (int s = start + wid; s < end; s += 4) {
        const float *kp, *vp;
        if (s == seqlen) {  // freshly computed token (cache never mutated)
            kp = g_qkv + b * 3072 + 2048 + kvh * HD;
            vp = g_qkv + b * 3072 + 2560 + kvh * HD;
        } else {
            int blk = bt[b * NBLK + (s >> 4)];
            int off = ((blk * BSZ + (s & 15)) * NKV + kvh) * HD;
            kp = kc + off; vp = vc + off;
        }
        float2 kv = *reinterpret_cast<const float2*>(kp + 2 * lane);
        float2 vv = *reinterpret_cast<const float2*>(vp + 2 * lane);
        float sc[GQ];
#pragma unroll
        for (int g = 0; g < GQ; g++) sc[g] = q[g].x * kv.x + q[g].y * kv.y;
#pragma unroll
        for (int o = 16; o > 0; o >>= 1) {
#pragma unroll
            for (int g = 0; g < GQ; g++) sc[g] += __shfl_xor_sync(0xffffffffu, sc[g], o);
        }
#pragma unroll
        for (int g = 0; g < GQ; g++) {
            float nm = fmaxf(m[g], sc[g]);
            float cor = __expf(m[g] - nm);
            float pw = __expf(sc[g] - nm);
            l[g] = l[g] * cor + pw;
            acc[g].x = acc[g].x * cor + pw * vv.x;
            acc[g].y = acc[g].y * cor + pw * vv.y;
            m[g] = nm;
        }
    }

    __shared__ float s_m[4][GQ], s_l[4][GQ], s_acc[4][GQ][HD];
#pragma unroll
    for (int g = 0; g < GQ; g++) {
        if (lane == 0) { s_m[wid][g] = m[g]; s_l[wid][g] = l[g]; }
        s_acc[wid][g][2 * lane]     = acc[g].x;
        s_acc[wid][g][2 * lane + 1] = acc[g].y;
    }
    __syncthreads();
    int pidx = (b * NKV + kvh) * NSPLIT + sp;
    for (int p = tid; p < GQ * HD; p += 128) {
        int g = p >> 6, d = p & 63;
        float M = fmaxf(fmaxf(s_m[0][g], s_m[1][g]), fmaxf(s_m[2][g], s_m[3][g]));
        float L = 0.f, A = 0.f;
#pragma unroll
        for (int w = 0; w < 4; w++) {
            float e = __expf(s_m[w][g] - M);
            L += s_l[w][g] * e;
            A += s_acc[w][g][d] * e;
        }
        g_pacc[pidx * 256 + p] = A;
        if (d == 0) { g_pm[pidx * GQ + g] = M; g_pl[pidx * GQ + g] = L; }
    }
}

__global__ __launch_bounds__(256) void attn_combine_kernel()
{
    int bk = blockIdx.x;             // b*NKV + kvh
    int t = threadIdx.x;             // 256 = GQ*HD
    int g = t >> 6, d = t & 63;
    float M = -1e30f;
    for (int sp = 0; sp < NSPLIT; sp++)
        M = fmaxf(M, g_pm[(bk * NSPLIT + sp) * GQ + g]);
    float L = 0.f, A = 0.f;
    for (int sp = 0; sp < NSPLIT; sp++) {
        float e = __expf(g_pm[(bk * NSPLIT + sp) * GQ + g] - M);
        L += g_pl[(bk * NSPLIT + sp) * GQ + g] * e;
        A += g_pacc[(bk * NSPLIT + sp) * 256 + t] * e;
    }
    int b = bk >> 3, kvh = bk & 7;
    g_attn[b * H + (kvh * GQ + g) * HD + d] = A / L;
}

// ---------------- launcher ----------------
static float* sym(const void* s) { void* p = nullptr; cudaGetSymbolAddress(&p, s); return (float*)p; }

extern "C" void kernel_launch(void* const* d_in, const int* in_sizes, int n_in,
                              void* d_out, int out_size)
{
    const float* x   = (const float*)d_in[0];
    const float* kc  = (const float*)d_in[1];
    const float* vc  = (const float*)d_in[2];
    const float* ln1 = (const float*)d_in[3];
    const float* qw  = (const float*)d_in[4];
    const float* kw  = (const float*)d_in[5];
    const float* vw  = (const float*)d_in[6];
    const float* ow  = (const float*)d_in[7];
    const float* ln2 = (const float*)d_in[8];
    const float* gw  = (const float*)d_in[9];
    const float* uw  = (const float*)d_in[10];
    const float* dw  = (const float*)d_in[11];
    const int*   bt  = (const int*)d_in[12];
    const int*   sl  = (const int*)d_in[13];
    float* out = (float*)d_out;

    float* a_normed = sym(g_normed);
    float* a_qkv    = sym(g_qkv);
    float* a_attn   = sym(g_attn);
    float* a_x1     = sym(g_x1);
    float* a_n2     = sym(g_n2);
    float* a_act    = sym(g_act);
    float* a_pqkv   = sym(p_qkv);
    float* a_po     = sym(p_o);
    float* a_pd     = sym(p_d);

    // 1. RMSNorm 1
    rmsnorm_kernel<<<BQ, 256>>>(x, ln1, a_normed);
    // 2. QKV projection (K-split 16 x KC=128)
    qkv_part_kernel<<<dim3(12, 16), 128>>>(qw, kw, vw);
    reduce_kernel<<<(BQ * 3072) / 256, 256>>>(a_pqkv, BQ * 3072, 16, nullptr, a_qkv);
    // 3. RoPE on q + k
    rope_kernel<<<BQ, 256>>>(sl);
    // 4. split-KV attention
    attn_kernel<<<dim3(NSPLIT, NKV, BQ), 128>>>(kc, vc, bt, sl);
    attn_combine_kernel<<<BQ * NKV, 256>>>();
    // 5. O projection + residual
    gemm_part_kernel<<<dim3(8, 16), 128>>>(a_attn, H, ow, H, a_po, 128);
    reduce_kernel<<<(BQ * H) / 256, 256>>>(a_po, BQ * H, 16, x, a_x1);
    // 6. RMSNorm 2
    rmsnorm_kernel<<<BQ, 256>>>(a_x1, ln2, a_n2);
    // 7. gate/up + SiLU
    gu_part_kernel<<<dim3(64, 8), 128>>>(gw, uw);
    gu_reduce_kernel<<<(BQ * INTER) / 256, 256>>>();
    // 8. down projection + residual -> out
    gemm_part_kernel<<<dim3(8, 32), 128>>>(a_act, INTER, dw, H, a_pd, 256);
    reduce_kernel<<<(BQ * H) / 256, 256>>>(a_pd, BQ * H, 32, a_x1, out);
}